// round 16
// baseline (speedup 1.0000x reference)
#include <cuda_runtime.h>
#include <math.h>

// Problem constants
#define Bn   2
#define HIDn 128
#define NVn  16
#define Hn   361
#define Wn   720
#define PADn 2
#define Hpn  (Hn + 2*PADn)      // 365
#define Wpn  (Wn + 2*PADn)      // 724
#define HWn  (Hn*Wn)            // 259920
#define ACO  (-0.75f)
#define TWOPI 6.28318530717958647692f
#define PIf  3.14159265358979323f
#define PIO2 1.5707963267948966f
#define PIO4 0.78539816339744831f

typedef unsigned long long ull;

// Scratch (static device arrays; no runtime allocation)
__device__ __align__(16) float g_pad[(size_t)Bn*NVn*Hpn*Wpn]; // padded proj
__device__ float g_y[(size_t)Bn*NVn*HWn];   // interp * dw_w + dw_b
__device__ float g_slat[Hn];
__device__ float g_clat[Hn];
__device__ float g_par[8];                  // dt, minLat, dLatInv, minLon, dLonInv
__device__ float g_dwv[2*NVn];              // dw_w | dw_b

// ---- packed fp32x2 helpers ------------------------------------------------
__device__ __forceinline__ ull pk2(float a, float b) {
    ull r; asm("mov.b64 %0, {%1, %2};" : "=l"(r) : "f"(a), "f"(b)); return r;
}
__device__ __forceinline__ void upk2(float& a, float& b, ull v) {
    asm("mov.b64 {%0, %1}, %2;" : "=f"(a), "=f"(b) : "l"(v));
}
__device__ __forceinline__ ull ffma2(ull a, ull b, ull c) {
    ull d; asm("fma.rn.f32x2 %0, %1, %2, %3;" : "=l"(d) : "l"(a), "l"(b), "l"(c)); return d;
}

// ---------------------------------------------------------------------------
// Kernel T (launch 0): per-latitude-row sincos table (361 entries)
// ---------------------------------------------------------------------------
__global__ void kT_tables(const float* __restrict__ latg) {
    int h = blockIdx.x * blockDim.x + threadIdx.x;
    if (h < Hn) {
        float s, c;
        sincosf(latg[(size_t)h * Wn], &s, &c);
        g_slat[h] = s;
        g_clat[h] = c;
    }
}

// ---------------------------------------------------------------------------
// Kernel L (launch 1): scalar params
// ---------------------------------------------------------------------------
__global__ void kL_par(const float* __restrict__ dtp,
                       const float* __restrict__ latg,
                       const float* __restrict__ lonp) {
    if (threadIdx.x == 0) {
        float minLat = latg[0];
        float maxLat = latg[(size_t)(Hn-1)*Wn];
        float minLon = lonp[0];
        float maxLon = lonp[Wn-1];
        g_par[0] = dtp[0];
        g_par[1] = minLat;
        g_par[2] = 1.0f / (maxLat - minLat);
        g_par[3] = minLon;
        g_par[4] = 1.0f / (maxLon - minLon);
    }
}

// ---------------------------------------------------------------------------
// Kernel W (launch 2): depthwise weights table
// ---------------------------------------------------------------------------
__global__ void kW_dw(const float* __restrict__ dww,
                      const float* __restrict__ dwb) {
    int i = threadIdx.x;
    if (i < NVn) {
        g_dwv[i] = dww[i];
        g_dwv[NVn + i] = dwb[i];
    }
}

// ---------------------------------------------------------------------------
// Kernel A (launch 3 — PROFILED): down projection (128 -> 16), 2 adjacent
// pixels per thread. o-pair weight packing: weights stored as
// (w[2j],w[2j+1]) pairs; one LDS.64 weight feeds TWO ffma2 (pixel A and B
// with broadcast-packed x). Halves LDS count AND crossbar bytes vs R15.
// ---------------------------------------------------------------------------
__global__ void kA_downproj(const float* __restrict__ x,
                            const float* __restrict__ down_w,
                            const float* __restrict__ down_b) {
    __shared__ ull s_wp[HIDn*(NVn/2)];   // [c][j]: (w[2j][c], w[2j+1][c])
    __shared__ ull s_bp[NVn/2];          // (b[2j], b[2j+1])
    for (int i = threadIdx.x; i < HIDn*(NVn/2); i += blockDim.x) {
        int j = i % (NVn/2), c = i / (NVn/2);
        s_wp[c*(NVn/2) + j] = pk2(down_w[(2*j)*HIDn + c], down_w[(2*j+1)*HIDn + c]);
    }
    if (threadIdx.x < NVn/2)
        s_bp[threadIdx.x] = pk2(down_b[2*threadIdx.x], down_b[2*threadIdx.x+1]);
    __syncthreads();

    int idx = blockIdx.x * blockDim.x + threadIdx.x;   // pair index
    if (idx >= Bn*(HWn/2)) return;
    int b = idx / (HWn/2);
    int r = (idx - b*(HWn/2)) * 2;     // even; pairs never straddle rows (Wn even)
    int h = r / Wn;
    int w = r - h*Wn;

    // accA[j] = (out[2j], out[2j+1]) for pixel r; accB same for pixel r+1
    ull accA[NVn/2], accB[NVn/2];
#pragma unroll
    for (int j = 0; j < NVn/2; j++) { accA[j] = s_bp[j]; accB[j] = s_bp[j]; }

    const float* xp = x + (size_t)b*HIDn*HWn + r;
#pragma unroll 4
    for (int c = 0; c < HIDn; c++) {
        float2 xq = *reinterpret_cast<const float2*>(xp + (size_t)c*HWn);
        ull xa = pk2(xq.x, xq.x);
        ull xb = pk2(xq.y, xq.y);
        const ull* wr = s_wp + c*(NVn/2);
#pragma unroll
        for (int j = 0; j < NVn/2; j++) {
            ull wv = wr[j];
            accA[j] = ffma2(xa, wv, accA[j]);
            accB[j] = ffma2(xb, wv, accB[j]);
        }
    }
    // transpose (o-pair, px) -> (px-pair, o) and store
#pragma unroll
    for (int j = 0; j < NVn/2; j++) {
        float a0, a1, b0, b1;
        upk2(a0, a1, accA[j]);   // a0 = out[2j]@r,   a1 = out[2j+1]@r
        upk2(b0, b1, accB[j]);   // b0 = out[2j]@r+1, b1 = out[2j+1]@r+1
        *reinterpret_cast<ull*>(
            &g_pad[(((size_t)(b*NVn + 2*j))*Hpn + (h + PADn))*Wpn + (w + PADn)])
            = pk2(a0, b0);
        *reinterpret_cast<ull*>(
            &g_pad[(((size_t)(b*NVn + 2*j+1))*Hpn + (h + PADn))*Wpn + (w + PADn)])
            = pk2(a1, b1);
    }
}

// ---------------------------------------------------------------------------
// Kernel B (launch 4): pole-row fix on proj (mean over longitude, broadcast).
// ---------------------------------------------------------------------------
__global__ void kB_polefix_proj() {
    int plane = blockIdx.x >> 1;
    int which = blockIdx.x & 1;
    int hrow  = which ? (Hn - 1) : 0;
    float* row = g_pad + ((size_t)plane*Hpn + (hrow + PADn))*Wpn + PADn;

    __shared__ float s[256];
    float sum = 0.f;
    for (int w = threadIdx.x; w < Wn; w += 256) sum += row[w];
    s[threadIdx.x] = sum;
    __syncthreads();
    for (int st = 128; st > 0; st >>= 1) {
        if (threadIdx.x < st) s[threadIdx.x] += s[threadIdx.x + st];
        __syncthreads();
    }
    float mean = s[0] * (1.0f / (float)Wn);
    for (int w = threadIdx.x; w < Wn; w += 256) row[w] = mean;
}

// ---------------------------------------------------------------------------
// Kernel C (launch 5): fill geo-cyclic halo — halo cells only.
// ---------------------------------------------------------------------------
#define HALO_PER_PLANE (4*Wpn + Hn*4)
__global__ void kC_halo() {
    int idx = blockIdx.x * blockDim.x + threadIdx.x;
    if (idx >= Bn*NVn*HALO_PER_PLANE) return;
    int plane = idx / HALO_PER_PLANE;
    int i = idx - plane*HALO_PER_PLANE;

    int rrow, pc;
    if (i < 2*Wpn) {                      // top 2 rows
        rrow = i / Wpn;
        pc = i - rrow*Wpn;
    } else if (i < 4*Wpn) {               // bottom 2 rows
        int j = i - 2*Wpn;
        rrow = Hpn - 2 + j / Wpn;
        pc = j - (j/Wpn)*Wpn;
    } else {                              // side columns of middle rows
        int j = i - 4*Wpn;
        rrow = PADn + (j >> 2);
        int k = j & 3;
        pc = (k < 2) ? k : (Wpn - 4 + k);
    }

    int cj;
    if (pc < PADn)            cj = Wn - PADn + pc;
    else if (pc >= PADn + Wn) cj = pc - PADn - Wn;
    else                      cj = pc - PADn;

    int sr;
    if (rrow < PADn) {
        sr = PADn - 1 - rrow;
        cj = (cj + Wn/2) % Wn;
    } else if (rrow >= PADn + Hn) {
        int t = rrow - (PADn + Hn);
        sr = Hn - 1 - t;
        cj = (cj + Wn/2) % Wn;
    } else {
        sr = rrow - PADn;
    }
    g_pad[((size_t)plane*Hpn + rrow)*Wpn + pc] =
        g_pad[((size_t)plane*Hpn + (sr + PADn))*Wpn + (cj + PADn)];
}

// ---------------------------------------------------------------------------
// fast transcendentals
// ---------------------------------------------------------------------------
__device__ __forceinline__ float sin_sm(float x) {        // |x| < ~0.1
    float x2 = x*x;
    return x * fmaf(x2, fmaf(x2, 8.3333333e-3f, -1.6666667e-1f), 1.0f);
}
__device__ __forceinline__ float cos_sm(float x) {
    float x2 = x*x;
    return fmaf(x2, fmaf(x2, 4.1666667e-2f, -0.5f), 1.0f);
}

// branchless atan2, err ~1e-7 rad
__device__ __forceinline__ float fast_atan2(float y, float x) {
    float ax = fabsf(x), ay = fabsf(y);
    float hi = fmaxf(ax, ay), lo = fminf(ax, ay);
    float t = __fdividef(lo, hi);              // [0,1]
    bool red = t > 0.41421356f;
    float xr = __fdividef(t - 1.0f, t + 1.0f);
    float p = red ? xr : t;
    float z = p * p;
    float poly = fmaf(fmaf(fmaf(fmaf(z, 8.05374449538e-2f, -1.38776856032e-1f), z,
                 1.99777106478e-1f), z, -3.33329491539e-1f), z * p, p);
    float r = red ? (poly + PIO4) : poly;
    r = (ay > ax) ? (PIO2 - r) : r;
    r = (x < 0.0f) ? (PIf - r) : r;
    return copysignf(r, y);
}

// branchless asin, err ~1e-6 rad
__device__ __forceinline__ float fast_asin(float x) {
    float a = fabsf(x);
    bool big = a > 0.5f;
    float zb = 0.5f * (1.0f - a);
    float z = big ? zb : a*a;
    float arg = big ? sqrtf(zb) : a;
    float p = arg * fmaf(z, fmaf(z, fmaf(z, fmaf(z, fmaf(z, fmaf(z,
              1.7352764e-2f, 2.2372159e-2f), 3.0381944e-2f), 4.4642857e-2f),
              7.5e-2f), 1.6666667e-1f), 1.0f);
    float r = big ? fmaf(-2.0f, p, PIO2) : p;
    return copysignf(r, x);
}

// ---------------------------------------------------------------------------
// Kernel D1 (launch 6): departure point + bicubic sample + depthwise scale.
// grid: (ceil(W/256), Bn*NVn*Hn); thread = one (plane, h, w). Measured 94.3us.
// ---------------------------------------------------------------------------
__global__ void kD1_sample(const float* __restrict__ U,
                           const float* __restrict__ Vf,
                           const float* __restrict__ lonp) {
    int w = blockIdx.x * blockDim.x + threadIdx.x;
    if (w >= Wn) return;
    int py = blockIdx.y;
    int plane = py / Hn;
    int h = py - plane*Hn;
    int v = plane & (NVn - 1);

    float dt      = g_par[0];
    float minLat  = g_par[1];
    float dLatInv = g_par[2];
    float minLon  = g_par[3];
    float dLonInv = g_par[4];

    float slg = g_slat[h];
    float clg = g_clat[h];
    float lo  = __ldg(lonp + w);

    size_t base = (size_t)plane*HWn + (size_t)h*Wn + w;
    float uu = U[base];
    float vv = Vf[base];
    float lon_pr = -uu * dt;
    float lat_pr = -vv * dt;
    float slp = sin_sm(lat_pr), clp = cos_sm(lat_pr);
    float sln = sin_sm(lon_pr), cln = cos_sm(lon_pr);

    float sin_lat = fmaf(slp, clg, clp*cln*slg);
    sin_lat = fminf(fmaxf(sin_lat, -1.0f + 1e-7f), 1.0f - 1e-7f);
    float lat_dep = fast_asin(sin_lat);
    float num = clp * sln;
    float den = clp*cln*clg - slp*slg;
    float lon_dep = lo + fast_atan2(num, den);
    float a = lon_dep + TWOPI;
    lon_dep = a - floorf(a * (1.0f/TWOPI)) * TWOPI;   // remainder(a, 2pi)

    float pix_x = (lon_dep - minLon) * dLonInv * (float)(Wn - 1);
    float pix_y = (lat_dep - minLat) * dLatInv * (float)(Hn - 1);
    // normalize/unnormalize round trip (align_corners=True), matches reference fp path
    float gx = 2.0f*((pix_x + (float)PADn)/(float)(Wpn - 1)) - 1.0f;
    float gy = 2.0f*((pix_y + (float)PADn)/(float)(Hpn - 1)) - 1.0f;
    float ix = (gx + 1.0f)*0.5f*(float)(Wpn - 1);
    float iy = (gy + 1.0f)*0.5f*(float)(Hpn - 1);

    float x0f = floorf(ix), y0f = floorf(iy);
    float tx = ix - x0f, ty = iy - y0f;
    int x0 = (int)x0f, y0 = (int)y0f;

    float wx0, wx1, wx2, wx3, wy0, wy1, wy2, wy3;
    {
        float t = tx, t1 = t + 1.0f, t2 = 1.0f - t, t3 = 2.0f - t;
        wx0 = ((ACO*t1 - 5.0f*ACO)*t1 + 8.0f*ACO)*t1 - 4.0f*ACO;
        wx1 = ((ACO + 2.0f)*t - (ACO + 3.0f))*t*t + 1.0f;
        wx2 = ((ACO + 2.0f)*t2 - (ACO + 3.0f))*t2*t2 + 1.0f;
        wx3 = ((ACO*t3 - 5.0f*ACO)*t3 + 8.0f*ACO)*t3 - 4.0f*ACO;
    }
    {
        float t = ty, t1 = t + 1.0f, t2 = 1.0f - t, t3 = 2.0f - t;
        wy0 = ((ACO*t1 - 5.0f*ACO)*t1 + 8.0f*ACO)*t1 - 4.0f*ACO;
        wy1 = ((ACO + 2.0f)*t - (ACO + 3.0f))*t*t + 1.0f;
        wy2 = ((ACO + 2.0f)*t2 - (ACO + 3.0f))*t2*t2 + 1.0f;
        wy3 = ((ACO*t3 - 5.0f*ACO)*t3 + 8.0f*ACO)*t3 - 4.0f*ACO;
    }

    const float* rp = g_pad + (size_t)plane*Hpn*Wpn + (size_t)(y0-1)*Wpn + (x0-1);
    float r0 = fmaf(rp[3], wx3, fmaf(rp[2], wx2, fmaf(rp[1], wx1, rp[0]*wx0)));
    rp += Wpn;
    float r1 = fmaf(rp[3], wx3, fmaf(rp[2], wx2, fmaf(rp[1], wx1, rp[0]*wx0)));
    rp += Wpn;
    float r2 = fmaf(rp[3], wx3, fmaf(rp[2], wx2, fmaf(rp[1], wx1, rp[0]*wx0)));
    rp += Wpn;
    float r3 = fmaf(rp[3], wx3, fmaf(rp[2], wx2, fmaf(rp[1], wx1, rp[0]*wx0)));
    float acc = fmaf(r3, wy3, fmaf(r2, wy2, fmaf(r1, wy1, r0*wy0)));

    g_y[base] = fmaf(acc, g_dwv[v], g_dwv[NVn + v]);
}

// ---------------------------------------------------------------------------
// Kernel D2 (launch 7): up projection (16 -> 128), 2 pixels/thread via packed
// fp32x2; exact R3 structure (LDS.64 weights).
// ---------------------------------------------------------------------------
__global__ void kD2_upproj(const float* __restrict__ upw,
                           const float* __restrict__ upb,
                           float* __restrict__ out) {
    __shared__ ull s_w2[HIDn*NVn];   // [o][v], broadcast-packed
    __shared__ float s_b[HIDn];
    for (int i = threadIdx.x; i < HIDn*NVn; i += blockDim.x) {
        float wv = upw[i];
        s_w2[i] = pk2(wv, wv);
    }
    for (int i = threadIdx.x; i < HIDn; i += blockDim.x) s_b[i] = upb[i];
    __syncthreads();

    int idx = blockIdx.x * blockDim.x + threadIdx.x;   // pair index
    if (idx >= Bn*(HWn/2)) return;
    int b = idx / (HWn/2);
    int r = (idx - b*(HWn/2)) * 2;

    ull yv[NVn];
    const float* yp = g_y + (size_t)b*NVn*HWn + r;
#pragma unroll
    for (int vq = 0; vq < NVn; vq++)
        yv[vq] = *reinterpret_cast<const ull*>(yp + (size_t)vq*HWn);

    float* op = out + (size_t)b*HIDn*HWn + r;
#pragma unroll 8
    for (int o = 0; o < HIDn; o++) {
        ull acc = pk2(s_b[o], s_b[o]);
        const ull* wr = s_w2 + o*NVn;
#pragma unroll
        for (int vq = 0; vq < NVn; vq++) acc = ffma2(yv[vq], wr[vq], acc);
        *reinterpret_cast<ull*>(op + (size_t)o*HWn) = acc;
    }
}

// ---------------------------------------------------------------------------
// Kernel E (launch 8): pole-row fix on output.
// ---------------------------------------------------------------------------
__global__ void kE_polefix_out(float* __restrict__ out) {
    int bo = blockIdx.x >> 1;
    int which = blockIdx.x & 1;
    float* row = out + (size_t)bo*HWn + (which ? (size_t)(Hn-1)*Wn : 0);

    __shared__ float s[256];
    float sum = 0.f;
    for (int w = threadIdx.x; w < Wn; w += 256) sum += row[w];
    s[threadIdx.x] = sum;
    __syncthreads();
    for (int st = 128; st > 0; st >>= 1) {
        if (threadIdx.x < st) s[threadIdx.x] += s[threadIdx.x + st];
        __syncthreads();
    }
    float mean = s[0] * (1.0f / (float)Wn);
    for (int w = threadIdx.x; w < Wn; w += 256) row[w] = mean;
}

// ---------------------------------------------------------------------------
extern "C" void kernel_launch(void* const* d_in, const int* in_sizes, int n_in,
                              void* d_out, int out_size) {
    const float* hidden = (const float*)d_in[0];
    const float* U      = (const float*)d_in[1];
    const float* V      = (const float*)d_in[2];
    const float* dt     = (const float*)d_in[3];
    const float* latg   = (const float*)d_in[4];
    const float* lonog  = (const float*)d_in[5];
    const float* down_w = (const float*)d_in[6];
    const float* down_b = (const float*)d_in[7];
    const float* dw_w   = (const float*)d_in[8];
    const float* dw_b   = (const float*)d_in[9];
    const float* up_w   = (const float*)d_in[10];
    const float* up_b   = (const float*)d_in[11];
    float* out = (float*)d_out;

    int nPairs = Bn*(HWn/2);                 // 259920
    kT_tables<<<2, 256>>>(latg);                                        // 0
    kL_par<<<1, 32>>>(dt, latg, lonog);                                 // 1
    kW_dw<<<1, 32>>>(dw_w, dw_b);                                       // 2
    kA_downproj<<<(nPairs + 255)/256, 256>>>(hidden, down_w, down_b);   // 3 (profiled)
    kB_polefix_proj<<<Bn*NVn*2, 256>>>();                               // 4
    int nHalo = Bn*NVn*HALO_PER_PLANE;       // 138,880
    kC_halo<<<(nHalo + 255)/256, 256>>>();                              // 5
    dim3 gD1((Wn + 255)/256, Bn*NVn*Hn);
    kD1_sample<<<gD1, 256>>>(U, V, lonog);                              // 6
    kD2_upproj<<<(nPairs + 255)/256, 256>>>(up_w, up_b, out);           // 7
    kE_polefix_out<<<Bn*HIDn*2, 256>>>(out);                            // 8
}

// round 17
// speedup vs baseline: 1.0629x; 1.0629x over previous
#include <cuda_runtime.h>
#include <math.h>

// Problem constants
#define Bn   2
#define HIDn 128
#define NVn  16
#define Hn   361
#define Wn   720
#define PADn 2
#define Hpn  (Hn + 2*PADn)      // 365
#define Wpn  (Wn + 2*PADn)      // 724
#define HWn  (Hn*Wn)            // 259920
#define ACO  (-0.75f)
#define TWOPI 6.28318530717958647692f
#define PIf  3.14159265358979323f
#define PIO2 1.5707963267948966f
#define PIO4 0.78539816339744831f

typedef unsigned long long ull;

// Scratch (static device arrays; no runtime allocation)
__device__ __align__(16) float g_pad[(size_t)Bn*NVn*Hpn*Wpn]; // padded proj
__device__ float g_y[(size_t)Bn*NVn*HWn];   // interp * dw_w + dw_b
__device__ float g_slat[Hn];
__device__ float g_clat[Hn];
__device__ float g_par[8];                  // dt, minLat, dLatInv, minLon, dLonInv
__device__ float g_dwv[2*NVn];              // dw_w | dw_b

// ---- packed fp32x2 helpers ------------------------------------------------
__device__ __forceinline__ ull pk2(float a, float b) {
    ull r; asm("mov.b64 %0, {%1, %2};" : "=l"(r) : "f"(a), "f"(b)); return r;
}
__device__ __forceinline__ ull ffma2(ull a, ull b, ull c) {
    ull d; asm("fma.rn.f32x2 %0, %1, %2, %3;" : "=l"(d) : "l"(a), "l"(b), "l"(c)); return d;
}

// ---------------------------------------------------------------------------
// Kernel T (launch 0): per-latitude-row sincos table (361 entries)
// ---------------------------------------------------------------------------
__global__ void kT_tables(const float* __restrict__ latg) {
    int h = blockIdx.x * blockDim.x + threadIdx.x;
    if (h < Hn) {
        float s, c;
        sincosf(latg[(size_t)h * Wn], &s, &c);
        g_slat[h] = s;
        g_clat[h] = c;
    }
}

// ---------------------------------------------------------------------------
// Kernel L (launch 1): scalar params
// ---------------------------------------------------------------------------
__global__ void kL_par(const float* __restrict__ dtp,
                       const float* __restrict__ latg,
                       const float* __restrict__ lonp) {
    if (threadIdx.x == 0) {
        float minLat = latg[0];
        float maxLat = latg[(size_t)(Hn-1)*Wn];
        float minLon = lonp[0];
        float maxLon = lonp[Wn-1];
        g_par[0] = dtp[0];
        g_par[1] = minLat;
        g_par[2] = 1.0f / (maxLat - minLat);
        g_par[3] = minLon;
        g_par[4] = 1.0f / (maxLon - minLon);
    }
}

// ---------------------------------------------------------------------------
// Kernel W (launch 2): depthwise weights table
// ---------------------------------------------------------------------------
__global__ void kW_dw(const float* __restrict__ dww,
                      const float* __restrict__ dwb) {
    int i = threadIdx.x;
    if (i < NVn) {
        g_dwv[i] = dww[i];
        g_dwv[NVn + i] = dwb[i];
    }
}

// ---------------------------------------------------------------------------
// Kernel A (launch 3 — PROFILED): down projection (128 -> 16), ONE pixel per
// thread (scalar acc, low regs -> high occupancy -> more outstanding LDGs).
// Weights as float4 LDS.128 broadcasts.
// ---------------------------------------------------------------------------
__global__ void kA_downproj(const float* __restrict__ x,
                            const float* __restrict__ down_w,
                            const float* __restrict__ down_b) {
    __shared__ __align__(16) float s_w[HIDn*NVn];   // [c][o]
    __shared__ float s_b[NVn];
    for (int i = threadIdx.x; i < HIDn*NVn; i += blockDim.x) {
        int o = i % NVn, c = i / NVn;
        s_w[c*NVn + o] = down_w[o*HIDn + c];
    }
    if (threadIdx.x < NVn) s_b[threadIdx.x] = down_b[threadIdx.x];
    __syncthreads();

    int idx = blockIdx.x * blockDim.x + threadIdx.x;   // pixel index
    if (idx >= Bn*HWn) return;
    int b = idx / HWn;
    int r = idx - b*HWn;
    int h = r / Wn;
    int w = r - h*Wn;

    float acc[NVn];
#pragma unroll
    for (int o = 0; o < NVn; o++) acc[o] = s_b[o];

    const float* xp = x + (size_t)b*HIDn*HWn + r;
#pragma unroll 4
    for (int c = 0; c < HIDn; c++) {
        float xv = __ldg(xp + (size_t)c*HWn);
        const float4* w4 = reinterpret_cast<const float4*>(s_w + c*NVn);
#pragma unroll
        for (int j = 0; j < NVn/4; j++) {
            float4 wq = w4[j];
            acc[4*j+0] = fmaf(xv, wq.x, acc[4*j+0]);
            acc[4*j+1] = fmaf(xv, wq.y, acc[4*j+1]);
            acc[4*j+2] = fmaf(xv, wq.z, acc[4*j+2]);
            acc[4*j+3] = fmaf(xv, wq.w, acc[4*j+3]);
        }
    }
#pragma unroll
    for (int o = 0; o < NVn; o++) {
        g_pad[(((size_t)(b*NVn + o))*Hpn + (h + PADn))*Wpn + (w + PADn)] = acc[o];
    }
}

// ---------------------------------------------------------------------------
// Kernel B (launch 4): pole-row fix on proj (mean over longitude, broadcast).
// ---------------------------------------------------------------------------
__global__ void kB_polefix_proj() {
    int plane = blockIdx.x >> 1;
    int which = blockIdx.x & 1;
    int hrow  = which ? (Hn - 1) : 0;
    float* row = g_pad + ((size_t)plane*Hpn + (hrow + PADn))*Wpn + PADn;

    __shared__ float s[256];
    float sum = 0.f;
    for (int w = threadIdx.x; w < Wn; w += 256) sum += row[w];
    s[threadIdx.x] = sum;
    __syncthreads();
    for (int st = 128; st > 0; st >>= 1) {
        if (threadIdx.x < st) s[threadIdx.x] += s[threadIdx.x + st];
        __syncthreads();
    }
    float mean = s[0] * (1.0f / (float)Wn);
    for (int w = threadIdx.x; w < Wn; w += 256) row[w] = mean;
}

// ---------------------------------------------------------------------------
// Kernel C (launch 5): fill geo-cyclic halo — halo cells only.
// ---------------------------------------------------------------------------
#define HALO_PER_PLANE (4*Wpn + Hn*4)
__global__ void kC_halo() {
    int idx = blockIdx.x * blockDim.x + threadIdx.x;
    if (idx >= Bn*NVn*HALO_PER_PLANE) return;
    int plane = idx / HALO_PER_PLANE;
    int i = idx - plane*HALO_PER_PLANE;

    int rrow, pc;
    if (i < 2*Wpn) {                      // top 2 rows
        rrow = i / Wpn;
        pc = i - rrow*Wpn;
    } else if (i < 4*Wpn) {               // bottom 2 rows
        int j = i - 2*Wpn;
        rrow = Hpn - 2 + j / Wpn;
        pc = j - (j/Wpn)*Wpn;
    } else {                              // side columns of middle rows
        int j = i - 4*Wpn;
        rrow = PADn + (j >> 2);
        int k = j & 3;
        pc = (k < 2) ? k : (Wpn - 4 + k);
    }

    int cj;
    if (pc < PADn)            cj = Wn - PADn + pc;
    else if (pc >= PADn + Wn) cj = pc - PADn - Wn;
    else                      cj = pc - PADn;

    int sr;
    if (rrow < PADn) {
        sr = PADn - 1 - rrow;
        cj = (cj + Wn/2) % Wn;
    } else if (rrow >= PADn + Hn) {
        int t = rrow - (PADn + Hn);
        sr = Hn - 1 - t;
        cj = (cj + Wn/2) % Wn;
    } else {
        sr = rrow - PADn;
    }
    g_pad[((size_t)plane*Hpn + rrow)*Wpn + pc] =
        g_pad[((size_t)plane*Hpn + (sr + PADn))*Wpn + (cj + PADn)];
}

// ---------------------------------------------------------------------------
// fast transcendentals
// ---------------------------------------------------------------------------
__device__ __forceinline__ float sin_sm(float x) {        // |x| < ~0.1
    float x2 = x*x;
    return x * fmaf(x2, fmaf(x2, 8.3333333e-3f, -1.6666667e-1f), 1.0f);
}
__device__ __forceinline__ float cos_sm(float x) {
    float x2 = x*x;
    return fmaf(x2, fmaf(x2, 4.1666667e-2f, -0.5f), 1.0f);
}

// branchless atan2, err ~1e-7 rad
__device__ __forceinline__ float fast_atan2(float y, float x) {
    float ax = fabsf(x), ay = fabsf(y);
    float hi = fmaxf(ax, ay), lo = fminf(ax, ay);
    float t = __fdividef(lo, hi);              // [0,1]
    bool red = t > 0.41421356f;
    float xr = __fdividef(t - 1.0f, t + 1.0f);
    float p = red ? xr : t;
    float z = p * p;
    float poly = fmaf(fmaf(fmaf(fmaf(z, 8.05374449538e-2f, -1.38776856032e-1f), z,
                 1.99777106478e-1f), z, -3.33329491539e-1f), z * p, p);
    float r = red ? (poly + PIO4) : poly;
    r = (ay > ax) ? (PIO2 - r) : r;
    r = (x < 0.0f) ? (PIf - r) : r;
    return copysignf(r, y);
}

// branchless asin, err ~1e-6 rad
__device__ __forceinline__ float fast_asin(float x) {
    float a = fabsf(x);
    bool big = a > 0.5f;
    float zb = 0.5f * (1.0f - a);
    float z = big ? zb : a*a;
    float arg = big ? sqrtf(zb) : a;
    float p = arg * fmaf(z, fmaf(z, fmaf(z, fmaf(z, fmaf(z, fmaf(z,
              1.7352764e-2f, 2.2372159e-2f), 3.0381944e-2f), 4.4642857e-2f),
              7.5e-2f), 1.6666667e-1f), 1.0f);
    float r = big ? fmaf(-2.0f, p, PIO2) : p;
    return copysignf(r, x);
}

// ---------------------------------------------------------------------------
// Kernel D1 (launch 6): departure point + bicubic sample + depthwise scale.
// grid: (ceil(W/256), Bn*NVn*Hn); thread = one (plane, h, w). Measured 94.3us.
// ---------------------------------------------------------------------------
__global__ void kD1_sample(const float* __restrict__ U,
                           const float* __restrict__ Vf,
                           const float* __restrict__ lonp) {
    int w = blockIdx.x * blockDim.x + threadIdx.x;
    if (w >= Wn) return;
    int py = blockIdx.y;
    int plane = py / Hn;
    int h = py - plane*Hn;
    int v = plane & (NVn - 1);

    float dt      = g_par[0];
    float minLat  = g_par[1];
    float dLatInv = g_par[2];
    float minLon  = g_par[3];
    float dLonInv = g_par[4];

    float slg = g_slat[h];
    float clg = g_clat[h];
    float lo  = __ldg(lonp + w);

    size_t base = (size_t)plane*HWn + (size_t)h*Wn + w;
    float uu = U[base];
    float vv = Vf[base];
    float lon_pr = -uu * dt;
    float lat_pr = -vv * dt;
    float slp = sin_sm(lat_pr), clp = cos_sm(lat_pr);
    float sln = sin_sm(lon_pr), cln = cos_sm(lon_pr);

    float sin_lat = fmaf(slp, clg, clp*cln*slg);
    sin_lat = fminf(fmaxf(sin_lat, -1.0f + 1e-7f), 1.0f - 1e-7f);
    float lat_dep = fast_asin(sin_lat);
    float num = clp * sln;
    float den = clp*cln*clg - slp*slg;
    float lon_dep = lo + fast_atan2(num, den);
    float a = lon_dep + TWOPI;
    lon_dep = a - floorf(a * (1.0f/TWOPI)) * TWOPI;   // remainder(a, 2pi)

    float pix_x = (lon_dep - minLon) * dLonInv * (float)(Wn - 1);
    float pix_y = (lat_dep - minLat) * dLatInv * (float)(Hn - 1);
    // normalize/unnormalize round trip (align_corners=True), matches reference fp path
    float gx = 2.0f*((pix_x + (float)PADn)/(float)(Wpn - 1)) - 1.0f;
    float gy = 2.0f*((pix_y + (float)PADn)/(float)(Hpn - 1)) - 1.0f;
    float ix = (gx + 1.0f)*0.5f*(float)(Wpn - 1);
    float iy = (gy + 1.0f)*0.5f*(float)(Hpn - 1);

    float x0f = floorf(ix), y0f = floorf(iy);
    float tx = ix - x0f, ty = iy - y0f;
    int x0 = (int)x0f, y0 = (int)y0f;

    float wx0, wx1, wx2, wx3, wy0, wy1, wy2, wy3;
    {
        float t = tx, t1 = t + 1.0f, t2 = 1.0f - t, t3 = 2.0f - t;
        wx0 = ((ACO*t1 - 5.0f*ACO)*t1 + 8.0f*ACO)*t1 - 4.0f*ACO;
        wx1 = ((ACO + 2.0f)*t - (ACO + 3.0f))*t*t + 1.0f;
        wx2 = ((ACO + 2.0f)*t2 - (ACO + 3.0f))*t2*t2 + 1.0f;
        wx3 = ((ACO*t3 - 5.0f*ACO)*t3 + 8.0f*ACO)*t3 - 4.0f*ACO;
    }
    {
        float t = ty, t1 = t + 1.0f, t2 = 1.0f - t, t3 = 2.0f - t;
        wy0 = ((ACO*t1 - 5.0f*ACO)*t1 + 8.0f*ACO)*t1 - 4.0f*ACO;
        wy1 = ((ACO + 2.0f)*t - (ACO + 3.0f))*t*t + 1.0f;
        wy2 = ((ACO + 2.0f)*t2 - (ACO + 3.0f))*t2*t2 + 1.0f;
        wy3 = ((ACO*t3 - 5.0f*ACO)*t3 + 8.0f*ACO)*t3 - 4.0f*ACO;
    }

    const float* rp = g_pad + (size_t)plane*Hpn*Wpn + (size_t)(y0-1)*Wpn + (x0-1);
    float r0 = fmaf(rp[3], wx3, fmaf(rp[2], wx2, fmaf(rp[1], wx1, rp[0]*wx0)));
    rp += Wpn;
    float r1 = fmaf(rp[3], wx3, fmaf(rp[2], wx2, fmaf(rp[1], wx1, rp[0]*wx0)));
    rp += Wpn;
    float r2 = fmaf(rp[3], wx3, fmaf(rp[2], wx2, fmaf(rp[1], wx1, rp[0]*wx0)));
    rp += Wpn;
    float r3 = fmaf(rp[3], wx3, fmaf(rp[2], wx2, fmaf(rp[1], wx1, rp[0]*wx0)));
    float acc = fmaf(r3, wy3, fmaf(r2, wy2, fmaf(r1, wy1, r0*wy0)));

    g_y[base] = fmaf(acc, g_dwv[v], g_dwv[NVn + v]);
}

// ---------------------------------------------------------------------------
// Kernel D2 (launch 7): up projection (16 -> 128), 2 pixels/thread via packed
// fp32x2; exact R3 structure (LDS.64 weights).
// ---------------------------------------------------------------------------
__global__ void kD2_upproj(const float* __restrict__ upw,
                           const float* __restrict__ upb,
                           float* __restrict__ out) {
    __shared__ ull s_w2[HIDn*NVn];   // [o][v], broadcast-packed
    __shared__ float s_b[HIDn];
    for (int i = threadIdx.x; i < HIDn*NVn; i += blockDim.x) {
        float wv = upw[i];
        s_w2[i] = pk2(wv, wv);
    }
    for (int i = threadIdx.x; i < HIDn; i += blockDim.x) s_b[i] = upb[i];
    __syncthreads();

    int idx = blockIdx.x * blockDim.x + threadIdx.x;   // pair index
    if (idx >= Bn*(HWn/2)) return;
    int b = idx / (HWn/2);
    int r = (idx - b*(HWn/2)) * 2;

    ull yv[NVn];
    const float* yp = g_y + (size_t)b*NVn*HWn + r;
#pragma unroll
    for (int vq = 0; vq < NVn; vq++)
        yv[vq] = *reinterpret_cast<const ull*>(yp + (size_t)vq*HWn);

    float* op = out + (size_t)b*HIDn*HWn + r;
#pragma unroll 8
    for (int o = 0; o < HIDn; o++) {
        ull acc = pk2(s_b[o], s_b[o]);
        const ull* wr = s_w2 + o*NVn;
#pragma unroll
        for (int vq = 0; vq < NVn; vq++) acc = ffma2(yv[vq], wr[vq], acc);
        *reinterpret_cast<ull*>(op + (size_t)o*HWn) = acc;
    }
}

// ---------------------------------------------------------------------------
// Kernel E (launch 8): pole-row fix on output.
// ---------------------------------------------------------------------------
__global__ void kE_polefix_out(float* __restrict__ out) {
    int bo = blockIdx.x >> 1;
    int which = blockIdx.x & 1;
    float* row = out + (size_t)bo*HWn + (which ? (size_t)(Hn-1)*Wn : 0);

    __shared__ float s[256];
    float sum = 0.f;
    for (int w = threadIdx.x; w < Wn; w += 256) sum += row[w];
    s[threadIdx.x] = sum;
    __syncthreads();
    for (int st = 128; st > 0; st >>= 1) {
        if (threadIdx.x < st) s[threadIdx.x] += s[threadIdx.x + st];
        __syncthreads();
    }
    float mean = s[0] * (1.0f / (float)Wn);
    for (int w = threadIdx.x; w < Wn; w += 256) row[w] = mean;
}

// ---------------------------------------------------------------------------
extern "C" void kernel_launch(void* const* d_in, const int* in_sizes, int n_in,
                              void* d_out, int out_size) {
    const float* hidden = (const float*)d_in[0];
    const float* U      = (const float*)d_in[1];
    const float* V      = (const float*)d_in[2];
    const float* dt     = (const float*)d_in[3];
    const float* latg   = (const float*)d_in[4];
    const float* lonog  = (const float*)d_in[5];
    const float* down_w = (const float*)d_in[6];
    const float* down_b = (const float*)d_in[7];
    const float* dw_w   = (const float*)d_in[8];
    const float* dw_b   = (const float*)d_in[9];
    const float* up_w   = (const float*)d_in[10];
    const float* up_b   = (const float*)d_in[11];
    float* out = (float*)d_out;

    int nPix = Bn*HWn;                       // 519,840
    int nPairs = Bn*(HWn/2);                 // 259,920
    kT_tables<<<2, 256>>>(latg);                                        // 0
    kL_par<<<1, 32>>>(dt, latg, lonog);                                 // 1
    kW_dw<<<1, 32>>>(dw_w, dw_b);                                       // 2
    kA_downproj<<<(nPix + 255)/256, 256>>>(hidden, down_w, down_b);     // 3 (profiled)
    kB_polefix_proj<<<Bn*NVn*2, 256>>>();                               // 4
    int nHalo = Bn*NVn*HALO_PER_PLANE;       // 138,880
    kC_halo<<<(nHalo + 255)/256, 256>>>();                              // 5
    dim3 gD1((Wn + 255)/256, Bn*NVn*Hn);
    kD1_sample<<<gD1, 256>>>(U, V, lonog);                              // 6
    kD2_upproj<<<(nPairs + 255)/256, 256>>>(up_w, up_b, out);           // 7
    kE_polefix_out<<<Bn*HIDn*2, 256>>>(out);                            // 8
}